// round 5
// baseline (speedup 1.0000x reference)
#include <cuda_runtime.h>
#include <cuda_bf16.h>
#include <cstdint>

#define Bc 8
#define Nc 1024
#define Hc 512
#define NHEADS 8
#define HD 64
#define LN_EPS 1e-5f

typedef __nv_bfloat16 bf16;

// ---------------- scratch ------------------------------------------------------
__device__ bf16  g_q[Bc * NHEADS * Nc * HD];             // [bh][n][d] bf16
__device__ bf16  g_k[Bc * NHEADS * Nc * HD];
__device__ bf16  g_z0[Bc * NHEADS * HD * Nc];            // v, d-major [bh][d][n]
__device__ bf16  g_P[(size_t)Bc * NHEADS * Nc * Nc];     // exp(scores) bf16, 128MB
__device__ float g_rowsum[Bc * NHEADS * Nc];
__device__ unsigned g_adjbits[Bc * Nc * 32];             // 1 bit per adj entry
__device__ float g_zB[Bc * NHEADS * Nc * HD];            // final z, token-major fp32

// ---------------- helpers ------------------------------------------------------
__device__ __forceinline__ unsigned f2tf(float x) {
    unsigned r;
    asm("cvt.rna.tf32.f32 %0, %1;" : "=r"(r) : "f"(x));
    return r;
}
__device__ __forceinline__ void mma_tf32(float c[4],
    unsigned a0, unsigned a1, unsigned a2, unsigned a3,
    unsigned b0, unsigned b1)
{
    asm("mma.sync.aligned.m16n8k8.row.col.f32.tf32.tf32.f32 "
        "{%0,%1,%2,%3},{%4,%5,%6,%7},{%8,%9},{%0,%1,%2,%3};"
        : "+f"(c[0]), "+f"(c[1]), "+f"(c[2]), "+f"(c[3])
        : "r"(a0), "r"(a1), "r"(a2), "r"(a3), "r"(b0), "r"(b1));
}
__device__ __forceinline__ void mma_bf16(float c[4],
    unsigned a0, unsigned a1, unsigned a2, unsigned a3,
    unsigned b0, unsigned b1)
{
    asm("mma.sync.aligned.m16n8k16.row.col.f32.bf16.bf16.f32 "
        "{%0,%1,%2,%3},{%4,%5,%6,%7},{%8,%9},{%0,%1,%2,%3};"
        : "+f"(c[0]), "+f"(c[1]), "+f"(c[2]), "+f"(c[3])
        : "r"(a0), "r"(a1), "r"(a2), "r"(a3), "r"(b0), "r"(b1));
}
__device__ __forceinline__ void cp16(unsigned smem_dst, const void* gsrc) {
    asm volatile("cp.async.cg.shared.global [%0], [%1], 16;"
                 :: "r"(smem_dst), "l"(gsrc));
}
__device__ __forceinline__ void cp_commit() {
    asm volatile("cp.async.commit_group;");
}
template<int N> __device__ __forceinline__ void cp_wait() {
    asm volatile("cp.async.wait_group %0;" :: "n"(N));
}

// ---------------- kernel 0: pack adjacency into bitmask ------------------------
__global__ __launch_bounds__(256) void pack_adj(
    const int* __restrict__ adj, unsigned* __restrict__ bits)
{
    int gt = blockIdx.x * 256 + threadIdx.x;
    int gw = gt >> 5;                      // word id 0..262143
    int lane = gt & 31;
    int row = gw >> 5;                     // b*1024+n
    int col = (gw & 31) * 32 + lane;
    int v = adj[(size_t)row * Nc + col];
    unsigned m = __ballot_sync(0xffffffffu, v != 0);
    if (lane == 0) bits[gw] = m;
}

// ---------------- kernel 1: fused QKV GEMM (tf32 in, bf16 out) -----------------
__global__ __launch_bounds__(256) void qkv_kernel(
    const float* __restrict__ X,
    const float* __restrict__ Wq, const float* __restrict__ bq,
    const float* __restrict__ Wk, const float* __restrict__ bk,
    const float* __restrict__ Wv, const float* __restrict__ bv,
    bf16* __restrict__ outq, bf16* __restrict__ outk, bf16* __restrict__ outv)
{
    const int which = blockIdx.z;
    const float* W    = which == 0 ? Wq : which == 1 ? Wk : Wv;
    const float* bias = which == 0 ? bq : which == 1 ? bk : bv;

    __shared__ float Xs[128][36];
    __shared__ float Ws[128][36];

    const int tid = threadIdx.x;
    const int wid = tid >> 5, lane = tid & 31;
    const int g = lane >> 2, t = lane & 3;
    const int warpM = (wid >> 1) * 32;
    const int warpN = (wid & 1) * 64;
    const int mBase = blockIdx.y * 128;
    const int nBase = blockIdx.x * 128;

    float acc[2][8][4] = {};

    for (int k0 = 0; k0 < Hc; k0 += 32) {
        #pragma unroll
        for (int it = 0; it < 4; it++) {
            int j = tid + it * 256;
            int r = j >> 3, c4 = (j & 7) * 4;
            *(float4*)&Xs[r][c4] = *(const float4*)&X[(size_t)(mBase + r) * Hc + k0 + c4];
            *(float4*)&Ws[r][c4] = *(const float4*)&W[(size_t)(nBase + r) * Hc + k0 + c4];
        }
        __syncthreads();
        #pragma unroll
        for (int ks = 0; ks < 32; ks += 8) {
            unsigned a[2][4], b[8][2];
            #pragma unroll
            for (int mf = 0; mf < 2; mf++) {
                int r0 = warpM + mf * 16 + g;
                a[mf][0] = f2tf(Xs[r0][ks + t]);
                a[mf][1] = f2tf(Xs[r0 + 8][ks + t]);
                a[mf][2] = f2tf(Xs[r0][ks + t + 4]);
                a[mf][3] = f2tf(Xs[r0 + 8][ks + t + 4]);
            }
            #pragma unroll
            for (int nf = 0; nf < 8; nf++) {
                int nr = warpN + nf * 8 + g;
                b[nf][0] = f2tf(Ws[nr][ks + t]);
                b[nf][1] = f2tf(Ws[nr][ks + t + 4]);
            }
            #pragma unroll
            for (int mf = 0; mf < 2; mf++)
                #pragma unroll
                for (int nf = 0; nf < 8; nf++)
                    mma_tf32(acc[mf][nf], a[mf][0], a[mf][1], a[mf][2], a[mf][3],
                             b[nf][0], b[nf][1]);
        }
        __syncthreads();
    }

    #pragma unroll
    for (int mf = 0; mf < 2; mf++)
        #pragma unroll
        for (int nf = 0; nf < 8; nf++)
            #pragma unroll
            for (int half = 0; half < 2; half++) {
                int row = mBase + warpM + mf * 16 + g + half * 8;
                int col = nBase + warpN + nf * 8 + 2 * t;
                float v0 = acc[mf][nf][half * 2 + 0] + bias[col];
                float v1 = acc[mf][nf][half * 2 + 1] + bias[col + 1];
                int btok = row >> 10, ntok = row & 1023;
                int h = col >> 6, d = col & 63;
                int bh = btok * NHEADS + h;
                if (which == 2) {
                    outv[((size_t)bh * HD + d) * Nc + ntok] = __float2bfloat16_rn(v0);
                    outv[((size_t)bh * HD + d + 1) * Nc + ntok] = __float2bfloat16_rn(v1);
                } else {
                    bf16* out = which == 0 ? outq : outk;
                    __nv_bfloat162 pr;
                    pr.x = __float2bfloat16_rn(v0);
                    pr.y = __float2bfloat16_rn(v1);
                    *(__nv_bfloat162*)&out[((size_t)bh * Nc + ntok) * HD + d] = pr;
                }
            }
}

// ---------------- kernel 2: scores (bf16 MMA) -> masked exp + rowsum -----------
__global__ __launch_bounds__(256) void scores_kernel(
    const bf16* __restrict__ q, const bf16* __restrict__ k,
    const unsigned* __restrict__ adjbits, bf16* __restrict__ P,
    float* __restrict__ rowsum)
{
    const int bh = blockIdx.z;
    const int b = bh >> 3;
    const int nBase = blockIdx.y * 128;
    const int mBase = blockIdx.x * 128;

    __shared__ uint32_t Qs[128][36];   // 64 bf16 (32 words) + pad
    __shared__ uint32_t Ks[128][36];

    const int tid = threadIdx.x;
    const int wid = tid >> 5, lane = tid & 31;
    const int g = lane >> 2, t = lane & 3;
    const int warpM = (wid >> 2) * 64;
    const int warpN = (wid & 3) * 32;

    const bf16* qb = q + (size_t)bh * Nc * HD;
    const bf16* kb = k + (size_t)bh * Nc * HD;

    // single load phase (K = 64 fits one tile)
    #pragma unroll
    for (int it = 0; it < 4; it++) {
        int j = tid + it * 256;
        int r = j >> 3, c = j & 7;                // 16B chunk c of row r
        *(uint4*)&Qs[r][c * 4] = *(const uint4*)&qb[(size_t)(nBase + r) * HD + c * 8];
        *(uint4*)&Ks[r][c * 4] = *(const uint4*)&kb[(size_t)(mBase + r) * HD + c * 8];
    }
    __syncthreads();

    float acc[4][4][4] = {};
    #pragma unroll
    for (int ks = 0; ks < 32; ks += 8) {          // 4 k16 steps
        unsigned a[4][4], bb[4][2];
        #pragma unroll
        for (int mf = 0; mf < 4; mf++) {
            int r0 = warpM + mf * 16 + g;
            a[mf][0] = Qs[r0][ks + t];
            a[mf][1] = Qs[r0 + 8][ks + t];
            a[mf][2] = Qs[r0][ks + t + 4];
            a[mf][3] = Qs[r0 + 8][ks + t + 4];
        }
        #pragma unroll
        for (int nf = 0; nf < 4; nf++) {
            int nr = warpN + nf * 8 + g;
            bb[nf][0] = Ks[nr][ks + t];
            bb[nf][1] = Ks[nr][ks + t + 4];
        }
        #pragma unroll
        for (int mf = 0; mf < 4; mf++)
            #pragma unroll
            for (int nf = 0; nf < 4; nf++)
                mma_bf16(acc[mf][nf], a[mf][0], a[mf][1], a[mf][2], a[mf][3],
                         bb[nf][0], bb[nf][1]);
    }

    const unsigned* bitsb = adjbits + (size_t)b * Nc * 32;
    const int wordIdx = (mBase + warpN) >> 5;
    bf16* Pb = P + (size_t)bh * Nc * Nc;

    #pragma unroll
    for (int mf = 0; mf < 4; mf++) {
        #pragma unroll
        for (int half = 0; half < 2; half++) {
            int row = nBase + warpM + mf * 16 + g + half * 8;
            unsigned mrow = bitsb[(size_t)row * 32 + wordIdx];
            float local = 0.f;
            #pragma unroll
            for (int nf = 0; nf < 4; nf++) {
                int col = mBase + warpN + nf * 8 + 2 * t;
                int bit = nf * 8 + 2 * t;
                float s0 = acc[mf][nf][half * 2 + 0];
                float s1 = acc[mf][nf][half * 2 + 1];
                float e0 = ((mrow >> bit) & 1u) ? __expf(s0) : 0.f;
                float e1 = ((mrow >> (bit + 1)) & 1u) ? __expf(s1) : 0.f;
                __nv_bfloat162 pr;
                pr.x = __float2bfloat16_rn(e0);
                pr.y = __float2bfloat16_rn(e1);
                *(__nv_bfloat162*)&Pb[(size_t)row * Nc + col] = pr;
                local += e0 + e1;
            }
            local += __shfl_xor_sync(0xffffffffu, local, 1);
            local += __shfl_xor_sync(0xffffffffu, local, 2);
            if (t == 0) atomicAdd(&rowsum[(size_t)bh * Nc + row], local);
        }
    }
}

// ---------------- kernel 3: ALL 4 hops fused (persistent per bh x d-slice) -----
// CTA = (bh, 32-d slice). z slice ping-pongs in smem (d-major). P streamed 4x.
#define ZROW_W 516                                // 1024 bf16 + 8 pad, in words
#define ZBUF_W (32 * ZROW_W)                      // 16512 words
#define PROW_W 68                                 // 128 bf16 + 8 pad
#define PSTAGE_W (128 * PROW_W)                   // 8704 words
#define HOPS_SMEM_W (2 * ZBUF_W + 2 * PSTAGE_W + 1024)
#define HOPS_SMEM (HOPS_SMEM_W * 4)               // 205824 bytes

__global__ __launch_bounds__(512, 1) void hops_kernel(
    const bf16* __restrict__ Pg, const float* __restrict__ rowsum,
    const bf16* __restrict__ z0_tr, float* __restrict__ zfinal)
{
    extern __shared__ __align__(16) char smem[];
    uint32_t* sw = (uint32_t*)smem;
    unsigned sbase = (unsigned)__cvta_generic_to_shared(smem);

    const int cid = blockIdx.x;          // 0..127
    const int bh = cid >> 1;
    const int ds = (cid & 1) * 32;
    const bf16* Pb = Pg + (size_t)bh * Nc * Nc;
    const bf16* z0 = z0_tr + ((size_t)bh * HD + ds) * Nc;   // 32 x 1024

    const int tid = threadIdx.x;
    const int wid = tid >> 5, lane = tid & 31;
    const int g = lane >> 2, t = lane & 3;
    const int warpM = (wid >> 1) * 16;   // 0..112 (within 128-row ntile)
    const int warpN = (wid & 1) * 16;    // 0 or 16 (within 32 d)

    float* invf = (float*)(sw + 2 * ZBUF_W + 2 * PSTAGE_W);
    for (int i = tid; i < Nc; i += 512)
        invf[i] = 0.9f / rowsum[(size_t)bh * Nc + i];

    // prologue: z0 slice -> buffer 0 (32 rows x 2048B)
    #pragma unroll
    for (int j = 0; j < 8; j++) {
        int c = tid + j * 512;           // 0..4095 16B chunks
        int d = c >> 7, off = c & 127;
        cp16(sbase + (d * ZROW_W) * 4 + off * 16, z0 + (size_t)d * Nc + off * 8);
    }
    cp_commit();

    const unsigned psb = sbase + 2 * ZBUF_W * 4;

    auto load_chunk = [&](int c, int s) {
        int nt = c >> 3, kc = c & 7;
        const bf16* src = Pb + (size_t)nt * 128 * Nc + kc * 128;
        unsigned dstb = psb + s * PSTAGE_W * 4;
        #pragma unroll
        for (int j = 0; j < 4; j++) {
            int e = tid + j * 512;       // 0..2047
            int r = e >> 4, off = e & 15;
            cp16(dstb + r * (PROW_W * 4) + off * 16, src + (size_t)r * Nc + off * 8);
        }
        cp_commit();
    };

    int zin = 0;
    for (int hop = 0; hop < 4; hop++) {
        load_chunk(0, 0);
        load_chunk(1, 1);
        float acc[2][4] = {};
        for (int c = 0; c < 64; c++) {
            if (c < 62) cp_wait<1>(); else cp_wait<0>();
            __syncthreads();
            const uint32_t* pc = sw + 2 * ZBUF_W + (c & 1) * PSTAGE_W;
            const uint32_t* zc = sw + zin * ZBUF_W;
            const int kwg = (c & 7) * 64;          // word offset within z row
            #pragma unroll
            for (int ks = 0; ks < 8; ks++) {
                int kwp = ks * 8;
                unsigned a0 = pc[(warpM + g) * PROW_W + kwp + t];
                unsigned a1 = pc[(warpM + g + 8) * PROW_W + kwp + t];
                unsigned a2 = pc[(warpM + g) * PROW_W + kwp + t + 4];
                unsigned a3 = pc[(warpM + g + 8) * PROW_W + kwp + t + 4];
                #pragma unroll
                for (int nf = 0; nf < 2; nf++) {
                    int d = warpN + nf * 8 + g;
                    unsigned b0 = zc[d * ZROW_W + kwg + kwp + t];
                    unsigned b1 = zc[d * ZROW_W + kwg + kwp + t + 4];
                    mma_bf16(acc[nf], a0, a1, a2, a3, b0, b1);
                }
            }
            __syncthreads();
            if (c + 2 < 64) load_chunk(c + 2, c & 1);
            if ((c & 7) == 7) {
                int nt = c >> 3;
                bf16* zob = (bf16*)(sw + (zin ^ 1) * ZBUF_W);
                #pragma unroll
                for (int nf = 0; nf < 2; nf++)
                    #pragma unroll
                    for (int half = 0; half < 2; half++) {
                        int n = nt * 128 + warpM + g + half * 8;
                        float sc = invf[n];
                        int d0 = warpN + nf * 8 + 2 * t;
                        float z00 = __bfloat162float(z0[(size_t)d0 * Nc + n]);
                        float z01 = __bfloat162float(z0[(size_t)(d0 + 1) * Nc + n]);
                        float v0 = acc[nf][half * 2 + 0] * sc + 0.1f * z00;
                        float v1 = acc[nf][half * 2 + 1] * sc + 0.1f * z01;
                        if (hop == 3) {
                            *(float2*)&zfinal[((size_t)bh * Nc + n) * HD + ds + d0] =
                                make_float2(v0, v1);
                        } else {
                            zob[d0 * (ZROW_W * 2) + n] = __float2bfloat16_rn(v0);
                            zob[(d0 + 1) * (ZROW_W * 2) + n] = __float2bfloat16_rn(v1);
                        }
                    }
                #pragma unroll
                for (int nf = 0; nf < 2; nf++)
                    #pragma unroll
                    for (int e = 0; e < 4; e++) acc[nf][e] = 0.f;
            }
        }
        __syncthreads();
        zin ^= 1;
    }
}

// ---------------- kernel 4: residual + layernorm ------------------------------
__global__ __launch_bounds__(256) void out_kernel(
    const float* __restrict__ x, const float* __restrict__ z,
    const float* __restrict__ gamma, const float* __restrict__ beta,
    float* __restrict__ out)
{
    const int row = blockIdx.x;
    const int b = row >> 10, n = row & (Nc - 1);
    const int t = threadIdx.x;
    __shared__ float red[256];

    float y[2];
    float s = 0.f;
    #pragma unroll
    for (int j = 0; j < 2; j++) {
        int idx = t + j * 256;
        int h = idx >> 6, d = idx & 63;
        y[j] = x[(size_t)row * Hc + idx] +
               z[(((size_t)b * NHEADS + h) * Nc + n) * HD + d];
        s += y[j];
    }
    red[t] = s; __syncthreads();
    #pragma unroll
    for (int st = 128; st > 0; st >>= 1) {
        if (t < st) red[t] += red[t + st];
        __syncthreads();
    }
    float mu = red[0] * (1.0f / Hc);
    __syncthreads();

    float vs = 0.f;
    #pragma unroll
    for (int j = 0; j < 2; j++) { float d0 = y[j] - mu; vs += d0 * d0; }
    red[t] = vs; __syncthreads();
    #pragma unroll
    for (int st = 128; st > 0; st >>= 1) {
        if (t < st) red[t] += red[t + st];
        __syncthreads();
    }
    float var = red[0] * (1.0f / Hc);
    float rstd = rsqrtf(var + LN_EPS);
    #pragma unroll
    for (int j = 0; j < 2; j++) {
        int idx = t + j * 256;
        out[(size_t)row * Hc + idx] = (y[j] - mu) * rstd * gamma[idx] + beta[idx];
    }
}

// ---------------- launch -------------------------------------------------------
extern "C" void kernel_launch(void* const* d_in, const int* in_sizes, int n_in,
                              void* d_out, int out_size)
{
    const float* x     = (const float*)d_in[0];
    const int*   adj   = (const int*)d_in[1];
    const float* Wq    = (const float*)d_in[2];
    const float* bq    = (const float*)d_in[3];
    const float* Wk    = (const float*)d_in[4];
    const float* bk    = (const float*)d_in[5];
    const float* Wv    = (const float*)d_in[6];
    const float* bv    = (const float*)d_in[7];
    const float* gamma = (const float*)d_in[8];
    const float* beta  = (const float*)d_in[9];
    float* out = (float*)d_out;

    float *prs, *pzB;
    bf16 *pq, *pk, *pz0, *pP;
    unsigned* pbits;
    cudaGetSymbolAddress((void**)&pq,   g_q);
    cudaGetSymbolAddress((void**)&pk,   g_k);
    cudaGetSymbolAddress((void**)&pz0,  g_z0);
    cudaGetSymbolAddress((void**)&pP,   g_P);
    cudaGetSymbolAddress((void**)&prs,  g_rowsum);
    cudaGetSymbolAddress((void**)&pbits, g_adjbits);
    cudaGetSymbolAddress((void**)&pzB,  g_zB);

    cudaFuncSetAttribute(hops_kernel,
        cudaFuncAttributeMaxDynamicSharedMemorySize, HOPS_SMEM);

    cudaMemsetAsync(prs, 0, (size_t)Bc * NHEADS * Nc * sizeof(float));
    pack_adj<<<(Bc * Nc * 32 * 32) / 256, 256>>>(adj, pbits);

    qkv_kernel<<<dim3(Hc / 128, (Bc * Nc) / 128, 3), 256>>>(
        x, Wq, bq, Wk, bk, Wv, bv, pq, pk, pz0);

    scores_kernel<<<dim3(Nc / 128, Nc / 128, Bc * NHEADS), 256>>>(
        pq, pk, pbits, pP, prs);

    hops_kernel<<<128, 512, HOPS_SMEM>>>(pP, prs, pz0, pzB);

    out_kernel<<<Bc * Nc, 256>>>(x, pzB, gamma, beta, out);
}

// round 6
// speedup vs baseline: 1.2092x; 1.2092x over previous
#include <cuda_runtime.h>
#include <cuda_bf16.h>
#include <cstdint>

#define Bc 8
#define Nc 1024
#define Hc 512
#define NHEADS 8
#define HD 64
#define LN_EPS 1e-5f

typedef __nv_bfloat16 bf16;

// ---------------- scratch ------------------------------------------------------
__device__ bf16  g_q[Bc * NHEADS * Nc * HD];             // [bh][n][d] bf16
__device__ bf16  g_k[Bc * NHEADS * Nc * HD];
__device__ bf16  g_z0[Bc * NHEADS * HD * Nc];            // v, d-major [bh][d][n]
__device__ bf16  g_P[(size_t)Bc * NHEADS * Nc * Nc];     // exp(scores) bf16, 128MB
__device__ float g_rowsum[Bc * NHEADS * Nc];
__device__ unsigned g_adjbits[Bc * Nc * 32];             // 1 bit per adj entry
__device__ bf16  g_zA[Bc * NHEADS * HD * Nc];            // d-major intermediates
__device__ bf16  g_zC[Bc * NHEADS * HD * Nc];
__device__ float g_zB[Bc * NHEADS * Nc * HD];            // final z, token-major fp32

// ---------------- helpers ------------------------------------------------------
__device__ __forceinline__ unsigned f2tf(float x) {
    unsigned r;
    asm("cvt.rna.tf32.f32 %0, %1;" : "=r"(r) : "f"(x));
    return r;
}
__device__ __forceinline__ void mma_tf32(float c[4],
    unsigned a0, unsigned a1, unsigned a2, unsigned a3,
    unsigned b0, unsigned b1)
{
    asm("mma.sync.aligned.m16n8k8.row.col.f32.tf32.tf32.f32 "
        "{%0,%1,%2,%3},{%4,%5,%6,%7},{%8,%9},{%0,%1,%2,%3};"
        : "+f"(c[0]), "+f"(c[1]), "+f"(c[2]), "+f"(c[3])
        : "r"(a0), "r"(a1), "r"(a2), "r"(a3), "r"(b0), "r"(b1));
}
__device__ __forceinline__ void mma_bf16(float c[4],
    unsigned a0, unsigned a1, unsigned a2, unsigned a3,
    unsigned b0, unsigned b1)
{
    asm("mma.sync.aligned.m16n8k16.row.col.f32.bf16.bf16.f32 "
        "{%0,%1,%2,%3},{%4,%5,%6,%7},{%8,%9},{%0,%1,%2,%3};"
        : "+f"(c[0]), "+f"(c[1]), "+f"(c[2]), "+f"(c[3])
        : "r"(a0), "r"(a1), "r"(a2), "r"(a3), "r"(b0), "r"(b1));
}
__device__ __forceinline__ void cp16(unsigned smem_dst, const void* gsrc) {
    asm volatile("cp.async.cg.shared.global [%0], [%1], 16;"
                 :: "r"(smem_dst), "l"(gsrc));
}
__device__ __forceinline__ void cp_commit() {
    asm volatile("cp.async.commit_group;");
}
template<int N> __device__ __forceinline__ void cp_wait() {
    asm volatile("cp.async.wait_group %0;" :: "n"(N));
}

// ---------------- kernel 0: pack adjacency into bitmask ------------------------
__global__ __launch_bounds__(256) void pack_adj(
    const int* __restrict__ adj, unsigned* __restrict__ bits)
{
    int gt = blockIdx.x * 256 + threadIdx.x;
    int gw = gt >> 5;
    int lane = gt & 31;
    int row = gw >> 5;
    int col = (gw & 31) * 32 + lane;
    int v = adj[(size_t)row * Nc + col];
    unsigned m = __ballot_sync(0xffffffffu, v != 0);
    if (lane == 0) bits[gw] = m;
}

// ---------------- kernel 1: fused QKV GEMM (tf32 in, bf16 out) -----------------
__global__ __launch_bounds__(256) void qkv_kernel(
    const float* __restrict__ X,
    const float* __restrict__ Wq, const float* __restrict__ bq,
    const float* __restrict__ Wk, const float* __restrict__ bk,
    const float* __restrict__ Wv, const float* __restrict__ bv,
    bf16* __restrict__ outq, bf16* __restrict__ outk, bf16* __restrict__ outv)
{
    const int which = blockIdx.z;
    const float* W    = which == 0 ? Wq : which == 1 ? Wk : Wv;
    const float* bias = which == 0 ? bq : which == 1 ? bk : bv;

    __shared__ float Xs[128][36];
    __shared__ float Ws[128][36];

    const int tid = threadIdx.x;
    const int wid = tid >> 5, lane = tid & 31;
    const int g = lane >> 2, t = lane & 3;
    const int warpM = (wid >> 1) * 32;
    const int warpN = (wid & 1) * 64;
    const int mBase = blockIdx.y * 128;
    const int nBase = blockIdx.x * 128;

    float acc[2][8][4] = {};

    for (int k0 = 0; k0 < Hc; k0 += 32) {
        #pragma unroll
        for (int it = 0; it < 4; it++) {
            int j = tid + it * 256;
            int r = j >> 3, c4 = (j & 7) * 4;
            *(float4*)&Xs[r][c4] = *(const float4*)&X[(size_t)(mBase + r) * Hc + k0 + c4];
            *(float4*)&Ws[r][c4] = *(const float4*)&W[(size_t)(nBase + r) * Hc + k0 + c4];
        }
        __syncthreads();
        #pragma unroll
        for (int ks = 0; ks < 32; ks += 8) {
            unsigned a[2][4], b[8][2];
            #pragma unroll
            for (int mf = 0; mf < 2; mf++) {
                int r0 = warpM + mf * 16 + g;
                a[mf][0] = f2tf(Xs[r0][ks + t]);
                a[mf][1] = f2tf(Xs[r0 + 8][ks + t]);
                a[mf][2] = f2tf(Xs[r0][ks + t + 4]);
                a[mf][3] = f2tf(Xs[r0 + 8][ks + t + 4]);
            }
            #pragma unroll
            for (int nf = 0; nf < 8; nf++) {
                int nr = warpN + nf * 8 + g;
                b[nf][0] = f2tf(Ws[nr][ks + t]);
                b[nf][1] = f2tf(Ws[nr][ks + t + 4]);
            }
            #pragma unroll
            for (int mf = 0; mf < 2; mf++)
                #pragma unroll
                for (int nf = 0; nf < 8; nf++)
                    mma_tf32(acc[mf][nf], a[mf][0], a[mf][1], a[mf][2], a[mf][3],
                             b[nf][0], b[nf][1]);
        }
        __syncthreads();
    }

    #pragma unroll
    for (int mf = 0; mf < 2; mf++)
        #pragma unroll
        for (int nf = 0; nf < 8; nf++)
            #pragma unroll
            for (int half = 0; half < 2; half++) {
                int row = mBase + warpM + mf * 16 + g + half * 8;
                int col = nBase + warpN + nf * 8 + 2 * t;
                float v0 = acc[mf][nf][half * 2 + 0] + bias[col];
                float v1 = acc[mf][nf][half * 2 + 1] + bias[col + 1];
                int btok = row >> 10, ntok = row & 1023;
                int h = col >> 6, d = col & 63;
                int bh = btok * NHEADS + h;
                if (which == 2) {
                    outv[((size_t)bh * HD + d) * Nc + ntok] = __float2bfloat16_rn(v0);
                    outv[((size_t)bh * HD + d + 1) * Nc + ntok] = __float2bfloat16_rn(v1);
                } else {
                    bf16* out = which == 0 ? outq : outk;
                    __nv_bfloat162 pr;
                    pr.x = __float2bfloat16_rn(v0);
                    pr.y = __float2bfloat16_rn(v1);
                    *(__nv_bfloat162*)&out[((size_t)bh * Nc + ntok) * HD + d] = pr;
                }
            }
}

// ---------------- kernel 2: scores (bf16 MMA) -> masked exp + rowsum -----------
__global__ __launch_bounds__(256) void scores_kernel(
    const bf16* __restrict__ q, const bf16* __restrict__ k,
    const unsigned* __restrict__ adjbits, bf16* __restrict__ P,
    float* __restrict__ rowsum)
{
    const int bh = blockIdx.z;
    const int b = bh >> 3;
    const int nBase = blockIdx.y * 128;
    const int mBase = blockIdx.x * 128;

    __shared__ uint32_t Qs[128][36];
    __shared__ uint32_t Ks[128][36];

    const int tid = threadIdx.x;
    const int wid = tid >> 5, lane = tid & 31;
    const int g = lane >> 2, t = lane & 3;
    const int warpM = (wid >> 2) * 64;
    const int warpN = (wid & 3) * 32;

    const bf16* qb = q + (size_t)bh * Nc * HD;
    const bf16* kb = k + (size_t)bh * Nc * HD;

    #pragma unroll
    for (int it = 0; it < 4; it++) {
        int j = tid + it * 256;
        int r = j >> 3, c = j & 7;
        *(uint4*)&Qs[r][c * 4] = *(const uint4*)&qb[(size_t)(nBase + r) * HD + c * 8];
        *(uint4*)&Ks[r][c * 4] = *(const uint4*)&kb[(size_t)(mBase + r) * HD + c * 8];
    }
    __syncthreads();

    float acc[4][4][4] = {};
    #pragma unroll
    for (int ks = 0; ks < 32; ks += 8) {
        unsigned a[4][4], bb[4][2];
        #pragma unroll
        for (int mf = 0; mf < 4; mf++) {
            int r0 = warpM + mf * 16 + g;
            a[mf][0] = Qs[r0][ks + t];
            a[mf][1] = Qs[r0 + 8][ks + t];
            a[mf][2] = Qs[r0][ks + t + 4];
            a[mf][3] = Qs[r0 + 8][ks + t + 4];
        }
        #pragma unroll
        for (int nf = 0; nf < 4; nf++) {
            int nr = warpN + nf * 8 + g;
            bb[nf][0] = Ks[nr][ks + t];
            bb[nf][1] = Ks[nr][ks + t + 4];
        }
        #pragma unroll
        for (int mf = 0; mf < 4; mf++)
            #pragma unroll
            for (int nf = 0; nf < 4; nf++)
                mma_bf16(acc[mf][nf], a[mf][0], a[mf][1], a[mf][2], a[mf][3],
                         bb[nf][0], bb[nf][1]);
    }

    const unsigned* bitsb = adjbits + (size_t)b * Nc * 32;
    const int wordIdx = (mBase + warpN) >> 5;
    bf16* Pb = P + (size_t)bh * Nc * Nc;

    #pragma unroll
    for (int mf = 0; mf < 4; mf++) {
        #pragma unroll
        for (int half = 0; half < 2; half++) {
            int row = nBase + warpM + mf * 16 + g + half * 8;
            unsigned mrow = bitsb[(size_t)row * 32 + wordIdx];
            float local = 0.f;
            #pragma unroll
            for (int nf = 0; nf < 4; nf++) {
                int col = mBase + warpN + nf * 8 + 2 * t;
                int bit = nf * 8 + 2 * t;
                float s0 = acc[mf][nf][half * 2 + 0];
                float s1 = acc[mf][nf][half * 2 + 1];
                float e0 = ((mrow >> bit) & 1u) ? __expf(s0) : 0.f;
                float e1 = ((mrow >> (bit + 1)) & 1u) ? __expf(s1) : 0.f;
                __nv_bfloat162 pr;
                pr.x = __float2bfloat16_rn(e0);
                pr.y = __float2bfloat16_rn(e1);
                *(__nv_bfloat162*)&Pb[(size_t)row * Nc + col] = pr;
                local += e0 + e1;
            }
            local += __shfl_xor_sync(0xffffffffu, local, 1);
            local += __shfl_xor_sync(0xffffffffu, local, 2);
            if (t == 0) atomicAdd(&rowsum[(size_t)bh * Nc + row], local);
        }
    }
}

// ---------------- kernel 3: hop, K=32 chunks, 4-stage pipeline, serpentine -----
#define PC_STRIDE 20                             // 32 bf16 (16 w) + 4 pad
#define PC_W (128 * PC_STRIDE)                   // 2560 words
#define ZC_STRIDE 20
#define ZC_W (64 * ZC_STRIDE)                    // 1280 words
#define STAGE_W (PC_W + ZC_W)                    // 3840 words
#define NSTAGE 4
#define HOP_SMEM (NSTAGE * STAGE_W * 4)          // 61440 bytes

template<bool LAST>
__global__ __launch_bounds__(256, 3) void hop_kernel4(
    const bf16* __restrict__ Pg, const float* __restrict__ rowsum,
    const bf16* __restrict__ zin_tr, const bf16* __restrict__ z0_tr,
    void* __restrict__ zout, int rev)
{
    extern __shared__ __align__(16) char smem[];
    unsigned sbase = (unsigned)__cvta_generic_to_shared(smem);
    const uint32_t* sw = (const uint32_t*)smem;

    int lin = blockIdx.y * gridDim.x + blockIdx.x;
    if (rev) lin = 511 - lin;
    const int bh = lin >> 3;
    const int mBase = (lin & 7) * 128;

    const bf16* Pb = Pg + (size_t)bh * Nc * Nc;
    const bf16* zi = zin_tr + (size_t)bh * HD * Nc;

    const int tid = threadIdx.x;
    const int wid = tid >> 5, lane = tid & 31;
    const int g = lane >> 2, t = lane & 3;
    const int warpM = (wid >> 1) * 32;
    const int warpN = (wid & 1) * 32;

    auto load_chunk = [&](int ck) {
        const int s = ck & (NSTAGE - 1);
        unsigned pbase = sbase + s * (STAGE_W * 4);
        unsigned zbase = pbase + PC_W * 4;
        const int k0 = ck * 32;
        #pragma unroll
        for (int j = 0; j < 2; j++) {
            int c = tid + j * 256;                 // 512 chunks of 16B (P)
            int r = c >> 2, off = c & 3;
            cp16(pbase + r * (PC_STRIDE * 4) + off * 16,
                 Pb + (size_t)(mBase + r) * Nc + k0 + off * 8);
        }
        {
            int c = tid;                           // 256 chunks of 16B (z)
            int d = c >> 2, off = c & 3;
            cp16(zbase + d * (ZC_STRIDE * 4) + off * 16,
                 zi + (size_t)d * Nc + k0 + off * 8);
        }
        cp_commit();
    };

    load_chunk(0);
    load_chunk(1);
    load_chunk(2);

    float acc[2][4][4] = {};

    #pragma unroll 4
    for (int c = 0; c < 32; c++) {
        if (c <= 29) cp_wait<2>();
        else if (c == 30) cp_wait<1>();
        else cp_wait<0>();
        __syncthreads();
        if (c + 3 < 32) load_chunk(c + 3);

        const uint32_t* pc = sw + (c & (NSTAGE - 1)) * STAGE_W;
        const uint32_t* zc = pc + PC_W;
        #pragma unroll
        for (int ks = 0; ks < 2; ks++) {
            const int kwp = ks * 8;
            unsigned a[2][4], bb[4][2];
            #pragma unroll
            for (int mf = 0; mf < 2; mf++) {
                int r0 = warpM + mf * 16 + g;
                a[mf][0] = pc[r0 * PC_STRIDE + kwp + t];
                a[mf][1] = pc[(r0 + 8) * PC_STRIDE + kwp + t];
                a[mf][2] = pc[r0 * PC_STRIDE + kwp + t + 4];
                a[mf][3] = pc[(r0 + 8) * PC_STRIDE + kwp + t + 4];
            }
            #pragma unroll
            for (int nf = 0; nf < 4; nf++) {
                int n = warpN + nf * 8 + g;
                bb[nf][0] = zc[n * ZC_STRIDE + kwp + t];
                bb[nf][1] = zc[n * ZC_STRIDE + kwp + t + 4];
            }
            #pragma unroll
            for (int mf = 0; mf < 2; mf++)
                #pragma unroll
                for (int nf = 0; nf < 4; nf++)
                    mma_bf16(acc[mf][nf], a[mf][0], a[mf][1], a[mf][2], a[mf][3],
                             bb[nf][0], bb[nf][1]);
        }
    }

    // ---- epilogue ----
    #pragma unroll
    for (int mf = 0; mf < 2; mf++)
        #pragma unroll
        for (int half = 0; half < 2; half++) {
            int row = mBase + warpM + mf * 16 + g + half * 8;
            float scale = 0.9f / rowsum[(size_t)bh * Nc + row];
            #pragma unroll
            for (int nf = 0; nf < 4; nf++) {
                int col = warpN + nf * 8 + 2 * t;
                float z00 = __bfloat162float(z0_tr[((size_t)bh * HD + col) * Nc + row]);
                float z01 = __bfloat162float(z0_tr[((size_t)bh * HD + col + 1) * Nc + row]);
                float v0 = acc[mf][nf][half * 2 + 0] * scale + 0.1f * z00;
                float v1 = acc[mf][nf][half * 2 + 1] * scale + 0.1f * z01;
                if (LAST) {
                    float* zf = (float*)zout;
                    *(float2*)&zf[((size_t)bh * Nc + row) * HD + col] = make_float2(v0, v1);
                } else {
                    bf16* zo = (bf16*)zout;
                    zo[((size_t)bh * HD + col) * Nc + row] = __float2bfloat16_rn(v0);
                    zo[((size_t)bh * HD + col + 1) * Nc + row] = __float2bfloat16_rn(v1);
                }
            }
        }
}

// ---------------- kernel 4: residual + layernorm ------------------------------
__global__ __launch_bounds__(256) void out_kernel(
    const float* __restrict__ x, const float* __restrict__ z,
    const float* __restrict__ gamma, const float* __restrict__ beta,
    float* __restrict__ out)
{
    const int row = blockIdx.x;
    const int b = row >> 10, n = row & (Nc - 1);
    const int t = threadIdx.x;
    __shared__ float red[256];

    float y[2];
    float s = 0.f;
    #pragma unroll
    for (int j = 0; j < 2; j++) {
        int idx = t + j * 256;
        int h = idx >> 6, d = idx & 63;
        y[j] = x[(size_t)row * Hc + idx] +
               z[(((size_t)b * NHEADS + h) * Nc + n) * HD + d];
        s += y[j];
    }
    red[t] = s; __syncthreads();
    #pragma unroll
    for (int st = 128; st > 0; st >>= 1) {
        if (t < st) red[t] += red[t + st];
        __syncthreads();
    }
    float mu = red[0] * (1.0f / Hc);
    __syncthreads();

    float vs = 0.f;
    #pragma unroll
    for (int j = 0; j < 2; j++) { float d0 = y[j] - mu; vs += d0 * d0; }
    red[t] = vs; __syncthreads();
    #pragma unroll
    for (int st = 128; st > 0; st >>= 1) {
        if (t < st) red[t] += red[t + st];
        __syncthreads();
    }
    float var = red[0] * (1.0f / Hc);
    float rstd = rsqrtf(var + LN_EPS);
    #pragma unroll
    for (int j = 0; j < 2; j++) {
        int idx = t + j * 256;
        out[(size_t)row * Hc + idx] = (y[j] - mu) * rstd * gamma[idx] + beta[idx];
    }
}

// ---------------- launch -------------------------------------------------------
extern "C" void kernel_launch(void* const* d_in, const int* in_sizes, int n_in,
                              void* d_out, int out_size)
{
    const float* x     = (const float*)d_in[0];
    const int*   adj   = (const int*)d_in[1];
    const float* Wq    = (const float*)d_in[2];
    const float* bq    = (const float*)d_in[3];
    const float* Wk    = (const float*)d_in[4];
    const float* bk    = (const float*)d_in[5];
    const float* Wv    = (const float*)d_in[6];
    const float* bv    = (const float*)d_in[7];
    const float* gamma = (const float*)d_in[8];
    const float* beta  = (const float*)d_in[9];
    float* out = (float*)d_out;

    float *prs, *pzB;
    bf16 *pq, *pk, *pz0, *pP, *pzA, *pzC;
    unsigned* pbits;
    cudaGetSymbolAddress((void**)&pq,   g_q);
    cudaGetSymbolAddress((void**)&pk,   g_k);
    cudaGetSymbolAddress((void**)&pz0,  g_z0);
    cudaGetSymbolAddress((void**)&pP,   g_P);
    cudaGetSymbolAddress((void**)&prs,  g_rowsum);
    cudaGetSymbolAddress((void**)&pbits, g_adjbits);
    cudaGetSymbolAddress((void**)&pzA,  g_zA);
    cudaGetSymbolAddress((void**)&pzC,  g_zC);
    cudaGetSymbolAddress((void**)&pzB,  g_zB);

    cudaFuncSetAttribute(hop_kernel4<false>,
        cudaFuncAttributeMaxDynamicSharedMemorySize, HOP_SMEM);
    cudaFuncSetAttribute(hop_kernel4<true>,
        cudaFuncAttributeMaxDynamicSharedMemorySize, HOP_SMEM);

    cudaMemsetAsync(prs, 0, (size_t)Bc * NHEADS * Nc * sizeof(float));
    pack_adj<<<(Bc * Nc * 32 * 32) / 256, 256>>>(adj, pbits);

    qkv_kernel<<<dim3(Hc / 128, (Bc * Nc) / 128, 3), 256>>>(
        x, Wq, bq, Wk, bk, Wv, bv, pq, pk, pz0);

    scores_kernel<<<dim3(Nc / 128, Nc / 128, Bc * NHEADS), 256>>>(
        pq, pk, pbits, pP, prs);

    dim3 gHop(Nc / 128, Bc * NHEADS);
    hop_kernel4<false><<<gHop, 256, HOP_SMEM>>>(pP, prs, pz0, pz0, pzA, 1);
    hop_kernel4<false><<<gHop, 256, HOP_SMEM>>>(pP, prs, pzA, pz0, pzC, 0);
    hop_kernel4<false><<<gHop, 256, HOP_SMEM>>>(pP, prs, pzC, pz0, pzA, 1);
    hop_kernel4<true><<<gHop, 256, HOP_SMEM>>>(pP, prs, pzA, pz0, pzB, 0);

    out_kernel<<<Bc * Nc, 256>>>(x, pzB, gamma, beta, out);
}

// round 7
// speedup vs baseline: 1.2989x; 1.0742x over previous
#include <cuda_runtime.h>
#include <cuda_bf16.h>
#include <cstdint>

#define Bc 8
#define Nc 1024
#define Hc 512
#define NHEADS 8
#define HD 64
#define LN_EPS 1e-5f

typedef __nv_bfloat16 bf16;

// ---------------- scratch ------------------------------------------------------
__device__ bf16  g_xb[Bc * Nc * Hc];                     // x in bf16
__device__ bf16  g_wb[3 * Hc * Hc];                      // Wq|Wk|Wv in bf16
__device__ bf16  g_q[Bc * NHEADS * Nc * HD];             // [bh][n][d] bf16
__device__ bf16  g_k[Bc * NHEADS * Nc * HD];
__device__ bf16  g_z0[Bc * NHEADS * HD * Nc];            // v, d-major [bh][d][n]
__device__ bf16  g_P[(size_t)Bc * NHEADS * Nc * Nc];     // exp(scores) bf16, 128MB
__device__ float g_rowsum[Bc * NHEADS * Nc];
__device__ unsigned g_adjbits[Bc * Nc * 32];
__device__ bf16  g_zA[Bc * NHEADS * HD * Nc];            // d-major intermediates
__device__ bf16  g_zC[Bc * NHEADS * HD * Nc];
__device__ float g_zB[Bc * NHEADS * Nc * HD];            // final z, token-major fp32

// ---------------- helpers ------------------------------------------------------
__device__ __forceinline__ void mma_bf16(float c[4],
    unsigned a0, unsigned a1, unsigned a2, unsigned a3,
    unsigned b0, unsigned b1)
{
    asm("mma.sync.aligned.m16n8k16.row.col.f32.bf16.bf16.f32 "
        "{%0,%1,%2,%3},{%4,%5,%6,%7},{%8,%9},{%0,%1,%2,%3};"
        : "+f"(c[0]), "+f"(c[1]), "+f"(c[2]), "+f"(c[3])
        : "r"(a0), "r"(a1), "r"(a2), "r"(a3), "r"(b0), "r"(b1));
}
__device__ __forceinline__ void cp16(unsigned smem_dst, const void* gsrc) {
    asm volatile("cp.async.cg.shared.global [%0], [%1], 16;"
                 :: "r"(smem_dst), "l"(gsrc));
}
__device__ __forceinline__ void cp_commit() {
    asm volatile("cp.async.commit_group;");
}
template<int N> __device__ __forceinline__ void cp_wait() {
    asm volatile("cp.async.wait_group %0;" :: "n"(N));
}
// swizzled word index within a 32-word (64 bf16) row
__device__ __forceinline__ int swz(int r, int kw) {
    return r * 32 + ((((kw >> 2) ^ (r & 7)) << 2) | (kw & 3));
}

// ---------------- kernel A: fp32 -> bf16 convert --------------------------------
__global__ __launch_bounds__(256) void cvt_bf16(
    const float4* __restrict__ in, __nv_bfloat162* __restrict__ out)
{
    int i = blockIdx.x * 256 + threadIdx.x;
    float4 v = in[i];
    __nv_bfloat162 a, b;
    a.x = __float2bfloat16_rn(v.x); a.y = __float2bfloat16_rn(v.y);
    b.x = __float2bfloat16_rn(v.z); b.y = __float2bfloat16_rn(v.w);
    out[2 * i] = a; out[2 * i + 1] = b;
}

// ---------------- kernel 0: pack adjacency into bitmask ------------------------
__global__ __launch_bounds__(256) void pack_adj(
    const int* __restrict__ adj, unsigned* __restrict__ bits)
{
    int gt = blockIdx.x * 256 + threadIdx.x;
    int gw = gt >> 5;
    int lane = gt & 31;
    int row = gw >> 5;
    int col = (gw & 31) * 32 + lane;
    int v = adj[(size_t)row * Nc + col];
    unsigned m = __ballot_sync(0xffffffffu, v != 0);
    if (lane == 0) bits[gw] = m;
}

// ---------------- kernel 1: QKV GEMM, all-bf16 ---------------------------------
__global__ __launch_bounds__(256) void qkv_kernel(
    const bf16* __restrict__ Xb, const bf16* __restrict__ Wb,
    const float* __restrict__ bq, const float* __restrict__ bk,
    const float* __restrict__ bv,
    bf16* __restrict__ outq, bf16* __restrict__ outk, bf16* __restrict__ outv)
{
    const int which = blockIdx.z;
    const bf16* W = Wb + (size_t)which * Hc * Hc;
    const float* bias = which == 0 ? bq : which == 1 ? bk : bv;

    __shared__ uint32_t Xs[128 * 36];
    __shared__ uint32_t Ws[128 * 36];

    const int tid = threadIdx.x;
    const int wid = tid >> 5, lane = tid & 31;
    const int g = lane >> 2, t = lane & 3;
    const int warpM = (wid >> 1) * 32;
    const int warpN = (wid & 1) * 64;
    const int mBase = blockIdx.y * 128;
    const int nBase = blockIdx.x * 128;

    float acc[2][8][4] = {};

    for (int k0 = 0; k0 < Hc; k0 += 64) {
        #pragma unroll
        for (int it = 0; it < 4; it++) {
            int j = tid + it * 256;
            int r = j >> 3, c = j & 7;
            *(uint4*)&Xs[r * 36 + c * 4] =
                *(const uint4*)&Xb[(size_t)(mBase + r) * Hc + k0 + c * 8];
            *(uint4*)&Ws[r * 36 + c * 4] =
                *(const uint4*)&W[(size_t)(nBase + r) * Hc + k0 + c * 8];
        }
        __syncthreads();
        #pragma unroll
        for (int ks = 0; ks < 32; ks += 8) {
            unsigned a[2][4], b[8][2];
            #pragma unroll
            for (int mf = 0; mf < 2; mf++) {
                int r0 = warpM + mf * 16 + g;
                a[mf][0] = Xs[r0 * 36 + ks + t];
                a[mf][1] = Xs[(r0 + 8) * 36 + ks + t];
                a[mf][2] = Xs[r0 * 36 + ks + t + 4];
                a[mf][3] = Xs[(r0 + 8) * 36 + ks + t + 4];
            }
            #pragma unroll
            for (int nf = 0; nf < 8; nf++) {
                int nr = warpN + nf * 8 + g;
                b[nf][0] = Ws[nr * 36 + ks + t];
                b[nf][1] = Ws[nr * 36 + ks + t + 4];
            }
            #pragma unroll
            for (int mf = 0; mf < 2; mf++)
                #pragma unroll
                for (int nf = 0; nf < 8; nf++)
                    mma_bf16(acc[mf][nf], a[mf][0], a[mf][1], a[mf][2], a[mf][3],
                             b[nf][0], b[nf][1]);
        }
        __syncthreads();
    }

    #pragma unroll
    for (int mf = 0; mf < 2; mf++)
        #pragma unroll
        for (int nf = 0; nf < 8; nf++)
            #pragma unroll
            for (int half = 0; half < 2; half++) {
                int row = mBase + warpM + mf * 16 + g + half * 8;
                int col = nBase + warpN + nf * 8 + 2 * t;
                float v0 = acc[mf][nf][half * 2 + 0] + bias[col];
                float v1 = acc[mf][nf][half * 2 + 1] + bias[col + 1];
                int btok = row >> 10, ntok = row & 1023;
                int h = col >> 6, d = col & 63;
                int bh = btok * NHEADS + h;
                if (which == 2) {
                    outv[((size_t)bh * HD + d) * Nc + ntok] = __float2bfloat16_rn(v0);
                    outv[((size_t)bh * HD + d + 1) * Nc + ntok] = __float2bfloat16_rn(v1);
                } else {
                    bf16* out = which == 0 ? outq : outk;
                    __nv_bfloat162 pr;
                    pr.x = __float2bfloat16_rn(v0);
                    pr.y = __float2bfloat16_rn(v1);
                    *(__nv_bfloat162*)&out[((size_t)bh * Nc + ntok) * HD + d] = pr;
                }
            }
}

// ---------------- kernel 2: scores, row-stripe CTA -----------------------------
// CTA = (row-tile 128, bh). Q fragments hoisted; K double-buffered; rowsum direct.
#define SCQ_W (128 * 36)
#define SCK_W (128 * 36)
#define SC_SMEM ((SCQ_W + 2 * SCK_W + 128) * 4)

__global__ __launch_bounds__(256) void scores_kernel(
    const bf16* __restrict__ q, const bf16* __restrict__ k,
    const unsigned* __restrict__ adjbits, bf16* __restrict__ P,
    float* __restrict__ rowsum)
{
    extern __shared__ __align__(16) char smem[];
    uint32_t* Qs = (uint32_t*)smem;
    uint32_t* Ks = Qs + SCQ_W;
    float* rs = (float*)(Ks + 2 * SCK_W);
    unsigned sbase = (unsigned)__cvta_generic_to_shared(smem);
    unsigned ksbase = sbase + SCQ_W * 4;

    const int bh = blockIdx.y;
    const int b = bh >> 3;
    const int nBase = blockIdx.x * 128;

    const int tid = threadIdx.x;
    const int wid = tid >> 5, lane = tid & 31;
    const int g = lane >> 2, t = lane & 3;
    const int warpM = (wid >> 2) * 64;
    const int warpN = (wid & 3) * 32;

    const bf16* qb = q + (size_t)bh * Nc * HD;
    const bf16* kb = k + (size_t)bh * Nc * HD;

    if (tid < 128) rs[tid] = 0.f;

    #pragma unroll
    for (int it = 0; it < 4; it++) {
        int j = tid + it * 256;
        int r = j >> 3, c = j & 7;
        *(uint4*)&Qs[r * 36 + c * 4] =
            *(const uint4*)&qb[(size_t)(nBase + r) * HD + c * 8];
    }

    auto loadK = [&](int ct, int s) {
        unsigned base = ksbase + s * (SCK_W * 4);
        #pragma unroll
        for (int j = 0; j < 4; j++) {
            int e = tid + j * 256;
            int r = e >> 3, c = e & 7;
            cp16(base + r * (36 * 4) + c * 16,
                 kb + (size_t)(ct * 128 + r) * HD + c * 8);
        }
        cp_commit();
    };
    loadK(0, 0);
    loadK(1, 1);
    __syncthreads();

    // hoist Q fragments (constant across all column tiles)
    unsigned a[4][4];
    #pragma unroll
    for (int mf = 0; mf < 4; mf++) {
        int r0 = warpM + mf * 16 + g;
        a[mf][0] = Qs[r0 * 36 + 0];        // filled per-ks below instead
    }
    // Q fragment per k-step: 4 ks x (4 mf x 4) -- load all once: 64 regs too many.
    // Instead hold per-ks on the fly from smem (Qs stays valid all kernel).

    const unsigned* bitsb = adjbits + (size_t)b * Nc * 32;
    bf16* Pb = P + (size_t)bh * Nc * Nc;

    float rloc[4][2] = {};

    for (int ct = 0; ct < 8; ct++) {
        if (ct < 7) cp_wait<1>(); else cp_wait<0>();
        __syncthreads();
        const uint32_t* kt = Ks + (ct & 1) * SCK_W;

        float acc[4][4][4] = {};
        #pragma unroll
        for (int ks = 0; ks < 32; ks += 8) {
            unsigned af[4][4], bb[4][2];
            #pragma unroll
            for (int mf = 0; mf < 4; mf++) {
                int r0 = warpM + mf * 16 + g;
                af[mf][0] = Qs[r0 * 36 + ks + t];
                af[mf][1] = Qs[(r0 + 8) * 36 + ks + t];
                af[mf][2] = Qs[r0 * 36 + ks + t + 4];
                af[mf][3] = Qs[(r0 + 8) * 36 + ks + t + 4];
            }
            #pragma unroll
            for (int nf = 0; nf < 4; nf++) {
                int nr = warpN + nf * 8 + g;
                bb[nf][0] = kt[nr * 36 + ks + t];
                bb[nf][1] = kt[nr * 36 + ks + t + 4];
            }
            #pragma unroll
            for (int mf = 0; mf < 4; mf++)
                #pragma unroll
                for (int nf = 0; nf < 4; nf++)
                    mma_bf16(acc[mf][nf], af[mf][0], af[mf][1], af[mf][2], af[mf][3],
                             bb[nf][0], bb[nf][1]);
        }

        const int wordIdx = ct * 4 + (warpN >> 5);
        #pragma unroll
        for (int mf = 0; mf < 4; mf++) {
            #pragma unroll
            for (int half = 0; half < 2; half++) {
                int row = nBase + warpM + mf * 16 + g + half * 8;
                unsigned mrow = bitsb[(size_t)row * 32 + wordIdx];
                float local = 0.f;
                #pragma unroll
                for (int nf = 0; nf < 4; nf++) {
                    int col = ct * 128 + warpN + nf * 8 + 2 * t;
                    int bit = nf * 8 + 2 * t;
                    float s0 = acc[mf][nf][half * 2 + 0];
                    float s1 = acc[mf][nf][half * 2 + 1];
                    float e0 = ((mrow >> bit) & 1u) ? __expf(s0) : 0.f;
                    float e1 = ((mrow >> (bit + 1)) & 1u) ? __expf(s1) : 0.f;
                    __nv_bfloat162 pr;
                    pr.x = __float2bfloat16_rn(e0);
                    pr.y = __float2bfloat16_rn(e1);
                    *(__nv_bfloat162*)&Pb[(size_t)row * Nc + col] = pr;
                    local += e0 + e1;
                }
                rloc[mf][half] += local;
            }
        }
        __syncthreads();
        if (ct + 2 < 8) loadK(ct + 2, ct & 1);
    }

    // reduce rloc across the quad (t) and accumulate into smem
    #pragma unroll
    for (int mf = 0; mf < 4; mf++)
        #pragma unroll
        for (int half = 0; half < 2; half++) {
            float v = rloc[mf][half];
            v += __shfl_xor_sync(0xffffffffu, v, 1);
            v += __shfl_xor_sync(0xffffffffu, v, 2);
            if (t == 0)
                atomicAdd(&rs[warpM + mf * 16 + g + half * 8], v);
        }
    __syncthreads();
    if (tid < 128)
        rowsum[(size_t)bh * Nc + nBase + tid] = rs[tid];
}

// ---------------- kernel 3: hop, K=64 chunks, 3-stage swizzled pipeline --------
#define PSW_W (128 * 32)                 // 4096 words
#define ZSW_W (64 * 32)                  // 2048 words
#define STG_W (PSW_W + ZSW_W)            // 6144 words = 24576 B
#define NST 3
#define HOP_SMEM (NST * STG_W * 4)       // 73728 bytes

template<bool LAST>
__global__ __launch_bounds__(256, 3) void hop_kernel5(
    const bf16* __restrict__ Pg, const float* __restrict__ rowsum,
    const bf16* __restrict__ zin_tr, const bf16* __restrict__ z0_tr,
    void* __restrict__ zout, int rev)
{
    extern __shared__ __align__(16) char smem[];
    unsigned sbase = (unsigned)__cvta_generic_to_shared(smem);
    const uint32_t* sw = (const uint32_t*)smem;

    int lin = blockIdx.y * gridDim.x + blockIdx.x;
    if (rev) lin = 511 - lin;
    const int bh = lin >> 3;
    const int mBase = (lin & 7) * 128;

    const bf16* Pb = Pg + (size_t)bh * Nc * Nc;
    const bf16* zi = zin_tr + (size_t)bh * HD * Nc;

    const int tid = threadIdx.x;
    const int wid = tid >> 5, lane = tid & 31;
    const int g = lane >> 2, t = lane & 3;
    const int warpM = (wid >> 1) * 32;
    const int warpN = (wid & 1) * 32;

    auto load_chunk = [&](int ck, int s) {
        unsigned pbase = sbase + s * (STG_W * 4);
        unsigned zbase = pbase + PSW_W * 4;
        const int k0 = ck * 64;
        #pragma unroll
        for (int j = 0; j < 4; j++) {
            int e = tid + j * 256;               // 1024 16B chunks of P
            int r = e >> 3, ch = e & 7;
            cp16(pbase + (r * 8 + (ch ^ (r & 7))) * 16,
                 Pb + (size_t)(mBase + r) * Nc + k0 + ch * 8);
        }
        #pragma unroll
        for (int j = 0; j < 2; j++) {
            int e = tid + j * 256;               // 512 16B chunks of z
            int d = e >> 3, ch = e & 7;
            cp16(zbase + (d * 8 + (ch ^ (d & 7))) * 16,
                 zi + (size_t)d * Nc + k0 + ch * 8);
        }
        cp_commit();
    };

    load_chunk(0, 0);
    load_chunk(1, 1);
    load_chunk(2, 2);

    float acc[2][4][4] = {};
    int st = 0;

    for (int c = 0; c < 16; c++) {
        if (c < 14) cp_wait<2>();
        else if (c == 14) cp_wait<1>();
        else cp_wait<0>();
        __syncthreads();

        const uint32_t* pc = sw + st * STG_W;
        const uint32_t* zc = pc + PSW_W;
        #pragma unroll
        for (int ks = 0; ks < 32; ks += 8) {
            unsigned a[2][4], bb[4][2];
            #pragma unroll
            for (int mf = 0; mf < 2; mf++) {
                int r0 = warpM + mf * 16 + g;
                a[mf][0] = pc[swz(r0, ks + t)];
                a[mf][1] = pc[swz(r0 + 8, ks + t)];
                a[mf][2] = pc[swz(r0, ks + t + 4)];
                a[mf][3] = pc[swz(r0 + 8, ks + t + 4)];
            }
            #pragma unroll
            for (int nf = 0; nf < 4; nf++) {
                int n = warpN + nf * 8 + g;
                bb[nf][0] = zc[swz(n, ks + t)];
                bb[nf][1] = zc[swz(n, ks + t + 4)];
            }
            #pragma unroll
            for (int mf = 0; mf < 2; mf++)
                #pragma unroll
                for (int nf = 0; nf < 4; nf++)
                    mma_bf16(acc[mf][nf], a[mf][0], a[mf][1], a[mf][2], a[mf][3],
                             bb[nf][0], bb[nf][1]);
        }
        __syncthreads();
        if (c + 3 < 16) load_chunk(c + 3, st);
        st = (st == NST - 1) ? 0 : st + 1;
    }

    // ---- epilogue ----
    #pragma unroll
    for (int mf = 0; mf < 2; mf++)
        #pragma unroll
        for (int half = 0; half < 2; half++) {
            int row = mBase + warpM + mf * 16 + g + half * 8;
            float scale = 0.9f / rowsum[(size_t)bh * Nc + row];
            #pragma unroll
            for (int nf = 0; nf < 4; nf++) {
                int col = warpN + nf * 8 + 2 * t;
                float z00 = __bfloat162float(z0_tr[((size_t)bh * HD + col) * Nc + row]);
                float z01 = __bfloat162float(z0_tr[((size_t)bh * HD + col + 1) * Nc + row]);
                float v0 = acc[mf][nf][half * 2 + 0] * scale + 0.1f * z00;
                float v1 = acc[mf][nf][half * 2 + 1] * scale + 0.1f * z01;
                if (LAST) {
                    float* zf = (float*)zout;
                    *(float2*)&zf[((size_t)bh * Nc + row) * HD + col] = make_float2(v0, v1);
                } else {
                    bf16* zo = (bf16*)zout;
                    zo[((size_t)bh * HD + col) * Nc + row] = __float2bfloat16_rn(v0);
                    zo[((size_t)bh * HD + col + 1) * Nc + row] = __float2bfloat16_rn(v1);
                }
            }
        }
}

// ---------------- kernel 4: residual + layernorm ------------------------------
__global__ __launch_bounds__(256) void out_kernel(
    const float* __restrict__ x, const float* __restrict__ z,
    const float* __restrict__ gamma, const float* __restrict__ beta,
    float* __restrict__ out)
{
    const int row = blockIdx.x;
    const int b = row >> 10, n = row & (Nc - 1);
    const int t = threadIdx.x;
    __shared__ float red[256];

    float y[2];
    float s = 0.f;
    #pragma unroll
    for (int j = 0; j < 2; j++) {
        int idx = t + j * 256;
        int h = idx >> 6, d = idx & 63;
        y[j] = x[(size_t)row * Hc + idx] +
               z[(((size_t)b * NHEADS + h) * Nc + n) * HD + d];
        s += y[j];
    }
    red[t] = s; __syncthreads();
    #pragma unroll
    for (int st = 128; st > 0; st >>= 1) {
        if (t < st) red[t] += red[t + st];
        __syncthreads();
    }
    float mu = red[0] * (1.0f / Hc);
    __syncthreads();

    float vs = 0.f;
    #pragma unroll
    for (int j = 0; j < 2; j++) { float d0 = y[j] - mu; vs += d0 * d0; }
    red[t] = vs; __syncthreads();
    #pragma unroll
    for (int st = 128; st > 0; st >>= 1) {
        if (t < st) red[t] += red[t + st];
        __syncthreads();
    }
    float var = red[0] * (1.0f / Hc);
    float rstd = rsqrtf(var + LN_EPS);
    #pragma unroll
    for (int j = 0; j < 2; j++) {
        int idx = t + j * 256;
        out[(size_t)row * Hc + idx] = (y[j] - mu) * rstd * gamma[idx] + beta[idx];
    }
}

// ---------------- launch -------------------------------------------------------
extern "C" void kernel_launch(void* const* d_in, const int* in_sizes, int n_in,
                              void* d_out, int out_size)
{
    const float* x     = (const float*)d_in[0];
    const int*   adj   = (const int*)d_in[1];
    const float* Wq    = (const float*)d_in[2];
    const float* bq    = (const float*)d_in[3];
    const float* Wk    = (const float*)d_in[4];
    const float* bk    = (const float*)d_in[5];
    const float* Wv    = (const float*)d_in[6];
    const float* bv    = (const float*)d_in[7];
    const float* gamma = (const float*)d_in[8];
    const float* beta  = (const float*)d_in[9];
    float* out = (float*)d_out;

    float *prs, *pzB;
    bf16 *pxb, *pwb, *pq, *pk, *pz0, *pP, *pzA, *pzC;
    unsigned* pbits;
    cudaGetSymbolAddress((void**)&pxb,  g_xb);
    cudaGetSymbolAddress((void**)&pwb,  g_wb);
    cudaGetSymbolAddress((void**)&pq,   g_q);
    cudaGetSymbolAddress((void**)&pk,   g_k);
    cudaGetSymbolAddress((void**)&pz0,  g_z0);
    cudaGetSymbolAddress((void**)&pP,   g_P);
    cudaGetSymbolAddress((void**)&prs,  g_rowsum);
    cudaGetSymbolAddress((void**)&pbits, g_adjbits);
    cudaGetSymbolAddress((void**)&pzA,  g_zA);
    cudaGetSymbolAddress((void**)&pzC,  g_zC);
    cudaGetSymbolAddress((void**)&pzB,  g_zB);

    cudaFuncSetAttribute(scores_kernel,
        cudaFuncAttributeMaxDynamicSharedMemorySize, SC_SMEM);
    cudaFuncSetAttribute(hop_kernel5<false>,
        cudaFuncAttributeMaxDynamicSharedMemorySize, HOP_SMEM);
    cudaFuncSetAttribute(hop_kernel5<true>,
        cudaFuncAttributeMaxDynamicSharedMemorySize, HOP_SMEM);

    // converts + bitmask pack
    cvt_bf16<<<(Bc * Nc * Hc) / 1024, 256>>>((const float4*)x, (__nv_bfloat162*)pxb);
    cvt_bf16<<<(Hc * Hc) / 1024, 256>>>((const float4*)Wq, (__nv_bfloat162*)(pwb + 0 * Hc * Hc));
    cvt_bf16<<<(Hc * Hc) / 1024, 256>>>((const float4*)Wk, (__nv_bfloat162*)(pwb + 1 * Hc * Hc));
    cvt_bf16<<<(Hc * Hc) / 1024, 256>>>((const float4*)Wv, (__nv_bfloat162*)(pwb + 2 * Hc * Hc));
    pack_adj<<<(Bc * Nc * 32 * 32) / 256, 256>>>(adj, pbits);

    qkv_kernel<<<dim3(Hc / 128, (Bc * Nc) / 128, 3), 256>>>(
        pxb, pwb, bq, bk, bv, pq, pk, pz0);

    scores_kernel<<<dim3(Nc / 128, Bc * NHEADS), 256, SC_SMEM>>>(
        pq, pk, pbits, pP, prs);

    dim3 gHop(Nc / 128, Bc * NHEADS);
    hop_kernel5<false><<<gHop, 256, HOP_SMEM>>>(pP, prs, pz0, pz0, pzA, 1);
    hop_kernel5<false><<<gHop, 256, HOP_SMEM>>>(pP, prs, pzA, pz0, pzC, 0);
    hop_kernel5<false><<<gHop, 256, HOP_SMEM>>>(pP, prs, pzC, pz0, pzA, 1);
    hop_kernel5<true><<<gHop, 256, HOP_SMEM>>>(pP, prs, pzA, pz0, pzB, 0);

    out_kernel<<<Bc * Nc, 256>>>(x, pzB, gamma, beta, out);
}

// round 8
// speedup vs baseline: 1.3935x; 1.0728x over previous
#include <cuda_runtime.h>
#include <cuda_bf16.h>
#include <cstdint>

#define Bc 8
#define Nc 1024
#define Hc 512
#define NHEADS 8
#define HD 64
#define LN_EPS 1e-5f

typedef __nv_bfloat16 bf16;

// ---------------- scratch ------------------------------------------------------
__device__ bf16  g_xb[Bc * Nc * Hc];
__device__ bf16  g_wb[3 * Hc * Hc];
__device__ bf16  g_q[Bc * NHEADS * Nc * HD];             // [bh][n][d]
__device__ bf16  g_k[Bc * NHEADS * Nc * HD];
__device__ bf16  g_z0[Bc * NHEADS * HD * Nc];            // v, d-major [bh][d][n]
__device__ bf16  g_P[(size_t)Bc * NHEADS * Nc * Nc];     // exp(scores), 128MB
__device__ float g_rowsum[Bc * NHEADS * Nc];
__device__ unsigned g_adjbits[Bc * Nc * 32];
__device__ bf16  g_zA[Bc * NHEADS * HD * Nc];            // d-major intermediates
__device__ bf16  g_zC[Bc * NHEADS * HD * Nc];
__device__ float g_zB[Bc * NHEADS * Nc * HD];            // final, token-major fp32

// ---------------- helpers ------------------------------------------------------
__device__ __forceinline__ void mma_bf16(float c[4],
    unsigned a0, unsigned a1, unsigned a2, unsigned a3,
    unsigned b0, unsigned b1)
{
    asm("mma.sync.aligned.m16n8k16.row.col.f32.bf16.bf16.f32 "
        "{%0,%1,%2,%3},{%4,%5,%6,%7},{%8,%9},{%0,%1,%2,%3};"
        : "+f"(c[0]), "+f"(c[1]), "+f"(c[2]), "+f"(c[3])
        : "r"(a0), "r"(a1), "r"(a2), "r"(a3), "r"(b0), "r"(b1));
}
__device__ __forceinline__ void cp16(unsigned smem_dst, const void* gsrc) {
    asm volatile("cp.async.cg.shared.global [%0], [%1], 16;"
                 :: "r"(smem_dst), "l"(gsrc));
}
__device__ __forceinline__ void cp_commit() {
    asm volatile("cp.async.commit_group;");
}
template<int N> __device__ __forceinline__ void cp_wait() {
    asm volatile("cp.async.wait_group %0;" :: "n"(N));
}
__device__ __forceinline__ int swz(int r, int kw) {
    return r * 32 + ((((kw >> 2) ^ (r & 7)) << 2) | (kw & 3));
}
__device__ __forceinline__ unsigned packbf(float x, float y) {
    __nv_bfloat162 p;
    p.x = __float2bfloat16_rn(x);
    p.y = __float2bfloat16_rn(y);
    return *(unsigned*)&p;
}

// ---------------- kernel A: fp32 -> bf16 convert --------------------------------
__global__ __launch_bounds__(256) void cvt_bf16(
    const float4* __restrict__ in, __nv_bfloat162* __restrict__ out)
{
    int i = blockIdx.x * 256 + threadIdx.x;
    float4 v = in[i];
    __nv_bfloat162 a, b;
    a.x = __float2bfloat16_rn(v.x); a.y = __float2bfloat16_rn(v.y);
    b.x = __float2bfloat16_rn(v.z); b.y = __float2bfloat16_rn(v.w);
    out[2 * i] = a; out[2 * i + 1] = b;
}

// ---------------- kernel 0: pack adjacency into bitmask ------------------------
__global__ __launch_bounds__(256) void pack_adj(
    const int* __restrict__ adj, unsigned* __restrict__ bits)
{
    int gt = blockIdx.x * 256 + threadIdx.x;
    int gw = gt >> 5;
    int lane = gt & 31;
    int row = gw >> 5;
    int col = (gw & 31) * 32 + lane;
    int v = adj[(size_t)row * Nc + col];
    unsigned m = __ballot_sync(0xffffffffu, v != 0);
    if (lane == 0) bits[gw] = m;
}

// ---------------- kernel 1: QKV GEMM, all-bf16 ---------------------------------
__global__ __launch_bounds__(256) void qkv_kernel(
    const bf16* __restrict__ Xb, const bf16* __restrict__ Wb,
    const float* __restrict__ bq, const float* __restrict__ bk,
    const float* __restrict__ bv,
    bf16* __restrict__ outq, bf16* __restrict__ outk, bf16* __restrict__ outv)
{
    const int which = blockIdx.z;
    const bf16* W = Wb + (size_t)which * Hc * Hc;
    const float* bias = which == 0 ? bq : which == 1 ? bk : bv;

    __shared__ uint32_t Xs[128 * 36];
    __shared__ uint32_t Ws[128 * 36];

    const int tid = threadIdx.x;
    const int wid = tid >> 5, lane = tid & 31;
    const int g = lane >> 2, t = lane & 3;
    const int warpM = (wid >> 1) * 32;
    const int warpN = (wid & 1) * 64;
    const int mBase = blockIdx.y * 128;
    const int nBase = blockIdx.x * 128;

    float acc[2][8][4] = {};

    for (int k0 = 0; k0 < Hc; k0 += 64) {
        #pragma unroll
        for (int it = 0; it < 4; it++) {
            int j = tid + it * 256;
            int r = j >> 3, c = j & 7;
            *(uint4*)&Xs[r * 36 + c * 4] =
                *(const uint4*)&Xb[(size_t)(mBase + r) * Hc + k0 + c * 8];
            *(uint4*)&Ws[r * 36 + c * 4] =
                *(const uint4*)&W[(size_t)(nBase + r) * Hc + k0 + c * 8];
        }
        __syncthreads();
        #pragma unroll
        for (int ks = 0; ks < 32; ks += 8) {
            unsigned a[2][4], b[8][2];
            #pragma unroll
            for (int mf = 0; mf < 2; mf++) {
                int r0 = warpM + mf * 16 + g;
                a[mf][0] = Xs[r0 * 36 + ks + t];
                a[mf][1] = Xs[(r0 + 8) * 36 + ks + t];
                a[mf][2] = Xs[r0 * 36 + ks + t + 4];
                a[mf][3] = Xs[(r0 + 8) * 36 + ks + t + 4];
            }
            #pragma unroll
            for (int nf = 0; nf < 8; nf++) {
                int nr = warpN + nf * 8 + g;
                b[nf][0] = Ws[nr * 36 + ks + t];
                b[nf][1] = Ws[nr * 36 + ks + t + 4];
            }
            #pragma unroll
            for (int mf = 0; mf < 2; mf++)
                #pragma unroll
                for (int nf = 0; nf < 8; nf++)
                    mma_bf16(acc[mf][nf], a[mf][0], a[mf][1], a[mf][2], a[mf][3],
                             b[nf][0], b[nf][1]);
        }
        __syncthreads();
    }

    #pragma unroll
    for (int mf = 0; mf < 2; mf++)
        #pragma unroll
        for (int nf = 0; nf < 8; nf++)
            #pragma unroll
            for (int half = 0; half < 2; half++) {
                int row = mBase + warpM + mf * 16 + g + half * 8;
                int col = nBase + warpN + nf * 8 + 2 * t;
                float v0 = acc[mf][nf][half * 2 + 0] + bias[col];
                float v1 = acc[mf][nf][half * 2 + 1] + bias[col + 1];
                int btok = row >> 10, ntok = row & 1023;
                int h = col >> 6, d = col & 63;
                int bh = btok * NHEADS + h;
                if (which == 2) {
                    outv[((size_t)bh * HD + d) * Nc + ntok] = __float2bfloat16_rn(v0);
                    outv[((size_t)bh * HD + d + 1) * Nc + ntok] = __float2bfloat16_rn(v1);
                } else {
                    bf16* out = which == 0 ? outq : outk;
                    __nv_bfloat162 pr;
                    pr.x = __float2bfloat16_rn(v0);
                    pr.y = __float2bfloat16_rn(v1);
                    *(__nv_bfloat162*)&out[((size_t)bh * Nc + ntok) * HD + d] = pr;
                }
            }
}

// ---------------- kernel 2: scores + hop1 fused --------------------------------
// CTA = (128-row stripe, bh). 8 warps x 16 rows each. Per ct (128 cols):
// scores MMA -> mask+exp -> P store -> feed exp fragments directly into P@z0 MMA.
#define FQ_W (128 * 36)
#define FK_W (128 * 36)
#define FZ_W (64 * 68)
#define FS_SMEM ((FQ_W + 2 * FK_W + 2 * FZ_W) * 4)       // 90112 B

__global__ __launch_bounds__(256, 2) void scores_hop1_kernel(
    const bf16* __restrict__ q, const bf16* __restrict__ k,
    const bf16* __restrict__ z0_tr, const unsigned* __restrict__ adjbits,
    bf16* __restrict__ P, float* __restrict__ rowsum, bf16* __restrict__ z1)
{
    extern __shared__ __align__(16) char smem[];
    uint32_t* Qs = (uint32_t*)smem;
    uint32_t* Ks = Qs + FQ_W;
    uint32_t* Zs = Ks + 2 * FK_W;
    unsigned sbase = (unsigned)__cvta_generic_to_shared(smem);
    unsigned kbase = sbase + FQ_W * 4;
    unsigned zbase = kbase + 2 * FK_W * 4;

    const int bh = blockIdx.y;
    const int b = bh >> 3;
    const int nBase = blockIdx.x * 128;

    const int tid = threadIdx.x;
    const int wid = tid >> 5, lane = tid & 31;
    const int g = lane >> 2, t = lane & 3;
    const int warpRow = wid * 16;

    const bf16* qb = q + (size_t)bh * Nc * HD;
    const bf16* kb = k + (size_t)bh * Nc * HD;
    const bf16* zi = z0_tr + (size_t)bh * HD * Nc;

    // Q tile (plain loads)
    #pragma unroll
    for (int it = 0; it < 4; it++) {
        int j = tid + it * 256;
        int r = j >> 3, c = j & 7;
        *(uint4*)&Qs[r * 36 + c * 4] =
            *(const uint4*)&qb[(size_t)(nBase + r) * HD + c * 8];
    }

    auto loadKZ = [&](int ct, int s) {
        unsigned kb2 = kbase + s * (FK_W * 4);
        #pragma unroll
        for (int j = 0; j < 4; j++) {
            int e = tid + j * 256;
            int r = e >> 3, c = e & 7;
            cp16(kb2 + r * (36 * 4) + c * 16,
                 kb + (size_t)(ct * 128 + r) * HD + c * 8);
        }
        unsigned zb2 = zbase + s * (FZ_W * 4);
        #pragma unroll
        for (int j = 0; j < 4; j++) {
            int e = tid + j * 256;
            int d = e >> 4, c = e & 15;
            cp16(zb2 + d * (68 * 4) + c * 16,
                 zi + (size_t)d * Nc + ct * 128 + c * 8);
        }
        cp_commit();
    };
    loadKZ(0, 0);
    loadKZ(1, 1);
    __syncthreads();

    // hoist Q fragments (Qs written before the cp.async groups; valid all kernel)
    unsigned qf[4][4];
    #pragma unroll
    for (int ks = 0; ks < 4; ks++) {
        int r0 = warpRow + g;
        qf[ks][0] = Qs[r0 * 36 + ks * 8 + t];
        qf[ks][1] = Qs[(r0 + 8) * 36 + ks * 8 + t];
        qf[ks][2] = Qs[r0 * 36 + ks * 8 + t + 4];
        qf[ks][3] = Qs[(r0 + 8) * 36 + ks * 8 + t + 4];
    }

    const unsigned* bitsb = adjbits + (size_t)b * Nc * 32;
    bf16* Pb = P + (size_t)bh * Nc * Nc;
    const int row_g = nBase + warpRow + g;
    const int row_h = row_g + 8;

    float accz[8][4] = {};
    float rs_g = 0.f, rs_h = 0.f;

    for (int ct = 0; ct < 8; ct++) {
        if (ct < 7) cp_wait<1>(); else cp_wait<0>();
        __syncthreads();
        const int buf = ct & 1;
        const uint32_t* kt = Ks + buf * FK_W;
        const uint32_t* zt = Zs + buf * FZ_W;

        #pragma unroll
        for (int half = 0; half < 2; half++) {
            // scores MMA: 16 rows x 64 cols
            float accs[8][4] = {};
            #pragma unroll
            for (int ks = 0; ks < 4; ks++) {
                unsigned bb[8][2];
                #pragma unroll
                for (int nf = 0; nf < 8; nf++) {
                    int nr = half * 64 + nf * 8 + g;
                    bb[nf][0] = kt[nr * 36 + ks * 8 + t];
                    bb[nf][1] = kt[nr * 36 + ks * 8 + t + 4];
                }
                #pragma unroll
                for (int nf = 0; nf < 8; nf++)
                    mma_bf16(accs[nf], qf[ks][0], qf[ks][1], qf[ks][2], qf[ks][3],
                             bb[nf][0], bb[nf][1]);
            }

            // mask + exp + pack + store P + rowsum
            unsigned prg[8], prh[8];
            unsigned mg0 = bitsb[(size_t)row_g * 32 + ct * 4 + half * 2];
            unsigned mg1 = bitsb[(size_t)row_g * 32 + ct * 4 + half * 2 + 1];
            unsigned mh0 = bitsb[(size_t)row_h * 32 + ct * 4 + half * 2];
            unsigned mh1 = bitsb[(size_t)row_h * 32 + ct * 4 + half * 2 + 1];
            #pragma unroll
            for (int nf = 0; nf < 8; nf++) {
                int cl = nf * 8 + 2 * t;          // 0..63 within half
                unsigned mg = (cl & 32) ? mg1 : mg0;
                unsigned mh = (cl & 32) ? mh1 : mh0;
                int bit = cl & 31;
                float e0 = ((mg >> bit) & 1u) ? __expf(accs[nf][0]) : 0.f;
                float e1 = ((mg >> (bit + 1)) & 1u) ? __expf(accs[nf][1]) : 0.f;
                float e2 = ((mh >> bit) & 1u) ? __expf(accs[nf][2]) : 0.f;
                float e3 = ((mh >> (bit + 1)) & 1u) ? __expf(accs[nf][3]) : 0.f;
                prg[nf] = packbf(e0, e1);
                prh[nf] = packbf(e2, e3);
                rs_g += e0 + e1;
                rs_h += e2 + e3;
                int col = ct * 128 + half * 64 + cl;
                *(unsigned*)&Pb[(size_t)row_g * Nc + col] = prg[nf];
                *(unsigned*)&Pb[(size_t)row_h * Nc + col] = prh[nf];
            }

            // z-MMA: A = exp fragments, B = z0 tile; k = this 64-col half
            #pragma unroll
            for (int kc = 0; kc < 4; kc++) {
                unsigned a0 = prg[2 * kc], a1 = prh[2 * kc];
                unsigned a2 = prg[2 * kc + 1], a3 = prh[2 * kc + 1];
                #pragma unroll
                for (int nd = 0; nd < 8; nd++) {
                    int d = nd * 8 + g;
                    unsigned b0 = zt[d * 68 + half * 32 + kc * 8 + t];
                    unsigned b1 = zt[d * 68 + half * 32 + kc * 8 + t + 4];
                    mma_bf16(accz[nd], a0, a1, a2, a3, b0, b1);
                }
            }
        }
        __syncthreads();
        if (ct + 2 < 8) loadKZ(ct + 2, buf);
    }

    // rowsum reduce over quad (cols split only by t within warp)
    rs_g += __shfl_xor_sync(0xffffffffu, rs_g, 1);
    rs_g += __shfl_xor_sync(0xffffffffu, rs_g, 2);
    rs_h += __shfl_xor_sync(0xffffffffu, rs_h, 1);
    rs_h += __shfl_xor_sync(0xffffffffu, rs_h, 2);
    if (t == 0) {
        rowsum[(size_t)bh * Nc + row_g] = rs_g;
        rowsum[(size_t)bh * Nc + row_h] = rs_h;
    }

    // hop1 epilogue: z1 = accz * 0.9/rowsum + 0.1*z0, d-major bf16
    float sc_g = 0.9f / rs_g, sc_h = 0.9f / rs_h;
    bf16* zo = z1 + (size_t)bh * HD * Nc;
    #pragma unroll
    for (int nd = 0; nd < 8; nd++) {
        int d0 = nd * 8 + 2 * t;
        float zg0 = __bfloat162float(zi[(size_t)d0 * Nc + row_g]);
        float zg1 = __bfloat162float(zi[(size_t)(d0 + 1) * Nc + row_g]);
        float zh0 = __bfloat162float(zi[(size_t)d0 * Nc + row_h]);
        float zh1 = __bfloat162float(zi[(size_t)(d0 + 1) * Nc + row_h]);
        zo[(size_t)d0 * Nc + row_g]       = __float2bfloat16_rn(accz[nd][0] * sc_g + 0.1f * zg0);
        zo[(size_t)(d0 + 1) * Nc + row_g] = __float2bfloat16_rn(accz[nd][1] * sc_g + 0.1f * zg1);
        zo[(size_t)d0 * Nc + row_h]       = __float2bfloat16_rn(accz[nd][2] * sc_h + 0.1f * zh0);
        zo[(size_t)(d0 + 1) * Nc + row_h] = __float2bfloat16_rn(accz[nd][3] * sc_h + 0.1f * zh1);
    }
}

// ---------------- kernel 3: hop, K=64 chunks, 2-stage swizzled, 4 CTA/SM -------
#define PSW_W (128 * 32)
#define ZSW_W (64 * 32)
#define STG_W (PSW_W + ZSW_W)            // 24576 B
#define HOP_SMEM (2 * STG_W * 4)         // 49152 B

template<bool LAST>
__global__ __launch_bounds__(256, 4) void hop_kernel6(
    const bf16* __restrict__ Pg, const float* __restrict__ rowsum,
    const bf16* __restrict__ zin_tr, const bf16* __restrict__ z0_tr,
    void* __restrict__ zout, int rev)
{
    extern __shared__ __align__(16) char smem[];
    unsigned sbase = (unsigned)__cvta_generic_to_shared(smem);
    const uint32_t* sw = (const uint32_t*)smem;

    int lin = blockIdx.y * gridDim.x + blockIdx.x;
    if (rev) lin = 511 - lin;
    const int bh = lin >> 3;
    const int mBase = (lin & 7) * 128;

    const bf16* Pb = Pg + (size_t)bh * Nc * Nc;
    const bf16* zi = zin_tr + (size_t)bh * HD * Nc;

    const int tid = threadIdx.x;
    const int wid = tid >> 5, lane = tid & 31;
    const int g = lane >> 2, t = lane & 3;
    const int warpM = (wid >> 1) * 32;
    const int warpN = (wid & 1) * 32;

    auto load_chunk = [&](int ck, int s) {
        unsigned pbase = sbase + s * (STG_W * 4);
        unsigned zbase = pbase + PSW_W * 4;
        const int k0 = ck * 64;
        #pragma unroll
        for (int j = 0; j < 4; j++) {
            int e = tid + j * 256;
            int r = e >> 3, ch = e & 7;
            cp16(pbase + (r * 8 + (ch ^ (r & 7))) * 16,
                 Pb + (size_t)(mBase + r) * Nc + k0 + ch * 8);
        }
        #pragma unroll
        for (int j = 0; j < 2; j++) {
            int e = tid + j * 256;
            int d = e >> 3, ch = e & 7;
            cp16(zbase + (d * 8 + (ch ^ (d & 7))) * 16,
                 zi + (size_t)d * Nc + k0 + ch * 8);
        }
        cp_commit();
    };

    load_chunk(0, 0);
    load_chunk(1, 1);

    float acc[2][4][4] = {};

    for (int c = 0; c < 16; c++) {
        if (c < 15) cp_wait<1>(); else cp_wait<0>();
        __syncthreads();
        const int st = c & 1;
        const uint32_t* pc = sw + st * STG_W;
        const uint32_t* zc = pc + PSW_W;
        #pragma unroll
        for (int ks = 0; ks < 32; ks += 8) {
            unsigned a[2][4], bb[4][2];
            #pragma unroll
            for (int mf = 0; mf < 2; mf++) {
                int r0 = warpM + mf * 16 + g;
                a[mf][0] = pc[swz(r0, ks + t)];
                a[mf][1] = pc[swz(r0 + 8, ks + t)];
                a[mf][2] = pc[swz(r0, ks + t + 4)];
                a[mf][3] = pc[swz(r0 + 8, ks + t + 4)];
            }
            #pragma unroll
            for (int nf = 0; nf < 4; nf++) {
                int n = warpN + nf * 8 + g;
                bb[nf][0] = zc[swz(n, ks + t)];
                bb[nf][1] = zc[swz(n, ks + t + 4)];
            }
            #pragma unroll
            for (int mf = 0; mf < 2; mf++)
                #pragma unroll
                for (int nf = 0; nf < 4; nf++)
                    mma_bf16(acc[mf][nf], a[mf][0], a[mf][1], a[mf][2], a[mf][3],
                             bb[nf][0], bb[nf][1]);
        }
        __syncthreads();
        if (c + 2 < 16) load_chunk(c + 2, st);
    }

    #pragma unroll
    for (int mf = 0; mf < 2; mf++)
        #pragma unroll
        for (int half = 0; half < 2; half++) {
            int row = mBase + warpM + mf * 16 + g + half * 8;
            float scale = 0.9f / rowsum[(size_t)bh * Nc + row];
            #pragma unroll
            for (int nf = 0; nf < 4; nf++) {
                int col = warpN + nf * 8 + 2 * t;
                float z00 = __bfloat162float(z0_tr[((size_t)bh * HD + col) * Nc + row]);
                float z01 = __bfloat162float(z0_tr[((size_t)bh * HD + col + 1) * Nc + row]);
                float v0 = acc[mf][nf][half * 2 + 0] * scale + 0.1f * z00;
                float v1 = acc[mf][nf][half * 2 + 1] * scale + 0.1f * z01;
                if (LAST) {
                    float* zf = (float*)zout;
                    *(float2*)&zf[((size_t)bh * Nc + row) * HD + col] = make_float2(v0, v1);
                } else {
                    bf16* zo = (bf16*)zout;
                    zo[((size_t)bh * HD + col) * Nc + row] = __float2bfloat16_rn(v0);
                    zo[((size_t)bh * HD + col + 1) * Nc + row] = __float2bfloat16_rn(v1);
                }
            }
        }
}

// ---------------- kernel 4: residual + layernorm ------------------------------
__global__ __launch_bounds__(256) void out_kernel(
    const float* __restrict__ x, const float* __restrict__ z,
    const float* __restrict__ gamma, const float* __restrict__ beta,
    float* __restrict__ out)
{
    const int row = blockIdx.x;
    const int b = row >> 10, n = row & (Nc - 1);
    const int t = threadIdx.x;
    __shared__ float red[256];

    float y[2];
    float s = 0.f;
    #pragma unroll
    for (int j = 0; j < 2; j++) {
        int idx = t + j * 256;
        int h = idx >> 6, d = idx & 63;
        y[j] = x[(size_t)row * Hc + idx] +
               z[(((size_t)b * NHEADS + h) * Nc + n) * HD + d];
        s += y[j];
    }
    red[t] = s; __syncthreads();
    #pragma unroll
    for (int st = 128; st > 0; st >>= 1) {
        if (t < st) red[t] += red[t + st];
        __syncthreads();
    }
    float mu = red[0] * (1.0f / Hc);
    __syncthreads();

    float vs = 0.f;
    #pragma unroll
    for (int j = 0; j < 2; j++) { float d0 = y[j] - mu; vs += d0 * d0; }
    red[t] = vs; __syncthreads();
    #pragma unroll
    for (int st = 128; st > 0; st >>= 1) {
        if (t < st) red[t] += red[t + st];
        __syncthreads();
    }
    float var = red[0] * (1.0f / Hc);
    float rstd = rsqrtf(var + LN_EPS);
    #pragma unroll
    for (int j = 0; j < 2; j++) {
        int idx = t + j * 256;
        out[(size_t)row * Hc + idx] = (y[j] - mu) * rstd * gamma[idx] + beta[idx];
    }
}

// ---------------- launch -------------------------------------------------------
extern "C" void kernel_launch(void* const* d_in, const int* in_sizes, int n_in,
                              void* d_out, int out_size)
{
    const float* x     = (const float*)d_in[0];
    const int*   adj   = (const int*)d_in[1];
    const float* Wq    = (const float*)d_in[2];
    const float* bq    = (const float*)d_in[3];
    const float* Wk    = (const float*)d_in[4];
    const float* bk    = (const float*)d_in[5];
    const float* Wv    = (const float*)d_in[6];
    const float* bv    = (const float*)d_in[7];
    const float* gamma = (const float*)d_in[8];
    const float* beta  = (const float*)d_in[9];
    float* out = (float*)d_out;

    float *prs, *pzB;
    bf16 *pxb, *pwb, *pq, *pk, *pz0, *pP, *pzA, *pzC;
    unsigned* pbits;
    cudaGetSymbolAddress((void**)&pxb,  g_xb);
    cudaGetSymbolAddress((void**)&pwb,  g_wb);
    cudaGetSymbolAddress((void**)&pq,   g_q);
    cudaGetSymbolAddress((void**)&pk,   g_k);
    cudaGetSymbolAddress((void**)&pz0,  g_z0);
    cudaGetSymbolAddress((void**)&pP,   g_P);
    cudaGetSymbolAddress((void**)&prs,  g_rowsum);
    cudaGetSymbolAddress((void**)&pbits, g_adjbits);
    cudaGetSymbolAddress((void**)&pzA,  g_zA);
    cudaGetSymbolAddress((void**)&pzC,  g_zC);
    cudaGetSymbolAddress((void**)&pzB,  g_zB);

    cudaFuncSetAttribute(scores_hop1_kernel,
        cudaFuncAttributeMaxDynamicSharedMemorySize, FS_SMEM);
    cudaFuncSetAttribute(hop_kernel6<false>,
        cudaFuncAttributeMaxDynamicSharedMemorySize, HOP_SMEM);
    cudaFuncSetAttribute(hop_kernel6<true>,
        cudaFuncAttributeMaxDynamicSharedMemorySize, HOP_SMEM);

    cvt_bf16<<<(Bc * Nc * Hc) / 1024, 256>>>((const float4*)x, (__nv_bfloat162*)pxb);
    cvt_bf16<<<(Hc * Hc) / 1024, 256>>>((const float4*)Wq, (__nv_bfloat162*)(pwb + 0 * Hc * Hc));
    cvt_bf16<<<(Hc * Hc) / 1024, 256>>>((const float4*)Wk, (__nv_bfloat162*)(pwb + 1 * Hc * Hc));
    cvt_bf16<<<(Hc * Hc) / 1024, 256>>>((const float4*)Wv, (__nv_bfloat162*)(pwb + 2 * Hc * Hc));
    pack_adj<<<(Bc * Nc * 32 * 32) / 256, 256>>>(adj, pbits);

    qkv_kernel<<<dim3(Hc / 128, (Bc * Nc) / 128, 3), 256>>>(
        pxb, pwb, bq, bk, bv, pq, pk, pz0);

    // scores + hop1 fused: writes P, rowsum, z1(=zA)
    scores_hop1_kernel<<<dim3(Nc / 128, Bc * NHEADS), 256, FS_SMEM>>>(
        pq, pk, pz0, pbits, pP, prs, pzA);

    dim3 gHop(Nc / 128, Bc * NHEADS);
    // serpentine: scores wrote P forward -> hop2 rev -> hop3 fwd -> hop4 rev
    hop_kernel6<false><<<gHop, 256, HOP_SMEM>>>(pP, prs, pzA, pz0, pzC, 1);
    hop_kernel6<false><<<gHop, 256, HOP_SMEM>>>(pP, prs, pzC, pz0, pzA, 0);
    hop_kernel6<true><<<gHop, 256, HOP_SMEM>>>(pP, prs, pzA, pz0, pzB, 1);

    out_kernel<<<Bc * Nc, 256>>>(x, pzB, gamma, beta, out);
}